// round 1
// baseline (speedup 1.0000x reference)
#include <cuda_runtime.h>

#define NN 50000
#define NE 800000
#define NH 4
#define DI 256
#define DO 64
#define CO 256   // NH * DO

// ---- scratch (device globals; no runtime allocation) ----
__device__ float g_feats[NN * CO];       // [n][h*64+o]
__device__ float g_as[NN * NH];
__device__ float g_ad[NN * NH];
__device__ float g_w[NE * NH];           // [e][h], float4-aligned per edge
__device__ int   g_deg[NN];
__device__ int   g_rowstart[NN + 1];
__device__ int   g_cursor[NN];
__device__ int   g_eidx[NE];
__device__ float g_Wcat[DI * CO];        // [d][h*64+o]
__device__ float g_bcat[CO];

// ---------------- weight repack ----------------
__global__ void prep_kernel(const float* __restrict__ Ws, const float* __restrict__ bs) {
    int i = blockIdx.x * blockDim.x + threadIdx.x;
    if (i < DI * CO) {
        int d = i >> 8, c = i & 255;
        int h = c >> 6, o = c & 63;
        g_Wcat[i] = Ws[(h * DI + d) * DO + o];
    }
    if (i < CO) {
        int h = i >> 6, o = i & 63;
        g_bcat[i] = bs[h * DO + o];
    }
}

__global__ void zero_deg_kernel() {
    int i = blockIdx.x * blockDim.x + threadIdx.x;
    if (i < NN) g_deg[i] = 0;
}

__global__ void count_kernel(const int* __restrict__ idx) {
    int e = blockIdx.x * blockDim.x + threadIdx.x;
    if (e < NE) atomicAdd(&g_deg[idx[e]], 1);
}

// single-block exclusive scan over degrees -> rowstart, cursor
__global__ void scan_kernel() {
    __shared__ int sd[1024];
    int tid = threadIdx.x;
    int carry = 0;
    for (int base = 0; base < NN; base += 1024) {
        int i = base + tid;
        int v = (i < NN) ? g_deg[i] : 0;
        sd[tid] = v;
        __syncthreads();
        for (int off = 1; off < 1024; off <<= 1) {
            int t = (tid >= off) ? sd[tid - off] : 0;
            __syncthreads();
            sd[tid] += t;
            __syncthreads();
        }
        if (i < NN) {
            int ex = carry + sd[tid] - v;
            g_rowstart[i] = ex;
            g_cursor[i] = ex;
        }
        carry += sd[1023];
        __syncthreads();
    }
    if (tid == 0) g_rowstart[NN] = carry;
}

// ---------------- projection GEMM: feats = x @ Wcat + bcat ----------------
// 64x64 tile, 256 threads, 4x4 register blocking, K-chunks of 16
__global__ void __launch_bounds__(256) gemm_kernel(const float* __restrict__ x) {
    __shared__ float As[16][68];   // [k][m]
    __shared__ float Bs[16][68];   // [k][n]
    int tid = threadIdx.x;
    int tx = tid & 15, ty = tid >> 4;
    int bm = blockIdx.y * 64, bn = blockIdx.x * 64;

    int lm = tid >> 2;          // 0..63  (A row)
    int lk = (tid & 3) * 4;     // k offset within chunk
    int bk = tid >> 4;          // 0..15  (B k-row)
    int bn4 = (tid & 15) * 4;

    float acc[4][4] = {};

    for (int k0 = 0; k0 < DI; k0 += 16) {
        float4 av = make_float4(0.f, 0.f, 0.f, 0.f);
        int row = bm + lm;
        if (row < NN) av = *(const float4*)(x + row * DI + k0 + lk);
        As[lk + 0][lm] = av.x;
        As[lk + 1][lm] = av.y;
        As[lk + 2][lm] = av.z;
        As[lk + 3][lm] = av.w;

        float4 bv = *(const float4*)(g_Wcat + (k0 + bk) * CO + bn + bn4);
        Bs[bk][bn4 + 0] = bv.x;
        Bs[bk][bn4 + 1] = bv.y;
        Bs[bk][bn4 + 2] = bv.z;
        Bs[bk][bn4 + 3] = bv.w;
        __syncthreads();

#pragma unroll
        for (int k = 0; k < 16; k++) {
            float a[4], b[4];
#pragma unroll
            for (int i = 0; i < 4; i++) a[i] = As[k][ty * 4 + i];
#pragma unroll
            for (int j = 0; j < 4; j++) b[j] = Bs[k][tx * 4 + j];
#pragma unroll
            for (int i = 0; i < 4; i++)
#pragma unroll
                for (int j = 0; j < 4; j++)
                    acc[i][j] += a[i] * b[j];
        }
        __syncthreads();
    }

#pragma unroll
    for (int i = 0; i < 4; i++) {
        int row = bm + ty * 4 + i;
        if (row < NN) {
#pragma unroll
            for (int j = 0; j < 4; j++) {
                int col = bn + tx * 4 + j;
                g_feats[row * CO + col] = acc[i][j] + g_bcat[col];
            }
        }
    }
}

// ---------------- per-node attention dots: a_s, a_d ----------------
__global__ void attn_kernel(const float* __restrict__ aw) {
    int gw = (blockIdx.x * blockDim.x + threadIdx.x) >> 5;
    int lane = threadIdx.x & 31;
    if (gw >= NN) return;
    const float* f = g_feats + gw * CO;
#pragma unroll
    for (int h = 0; h < NH; h++) {
        float f0 = f[h * 64 + lane];
        float f1 = f[h * 64 + 32 + lane];
        const float* a = aw + h * (2 * DO + 1);
        float vs = f0 * a[lane] + f1 * a[32 + lane];
        float vd = f0 * a[64 + lane] + f1 * a[96 + lane];
#pragma unroll
        for (int off = 16; off; off >>= 1) {
            vs += __shfl_down_sync(0xffffffffu, vs, off);
            vd += __shfl_down_sync(0xffffffffu, vd, off);
        }
        if (lane == 0) {
            g_as[gw * NH + h] = vs;
            g_ad[gw * NH + h] = vd;
        }
    }
}

// ---------------- edge weights + CSR fill ----------------
__global__ void edge_kernel(const int* __restrict__ idx, const float* __restrict__ elem,
                            const float* __restrict__ aw, const float* __restrict__ ab) {
    int e = blockIdx.x * blockDim.x + threadIdx.x;
    if (e >= NE) return;
    int s = idx[e];
    int d = idx[NE + e];
    float el = elem[e];
    float w[NH];
#pragma unroll
    for (int h = 0; h < NH; h++) {
        float sc = g_as[s * NH + h] + g_ad[d * NH + h]
                 + aw[h * (2 * DO + 1) + 2 * DO] * el + ab[h];
        sc = sc * (1.0f / 20.0f);
        w[h] = __expf(-fmaxf(sc, 0.0f));
    }
    *(float4*)(g_w + e * 4) = make_float4(w[0], w[1], w[2], w[3]);
    int pos = atomicAdd(&g_cursor[s], 1);
    g_eidx[pos] = e;
}

// ---------------- per-node gather + normalize ----------------
__global__ void __launch_bounds__(256) gather_kernel(const int* __restrict__ idx,
                                                     float* __restrict__ out) {
    int n = blockIdx.x;
    int t = threadIdx.x;          // 0..255 = h*64+o
    int h = t >> 6;
    int start = g_rowstart[n];
    int end = g_rowstart[n + 1];

    __shared__ int    dst_s[64];
    __shared__ float4 w_s[64];

    float acc = 0.f, wsum = 0.f;
    for (int base = start; base < end; base += 64) {
        int cnt = min(64, end - base);
        if (t < cnt) {
            int e = g_eidx[base + t];
            dst_s[t] = idx[NE + e];
            w_s[t] = *(const float4*)(g_w + e * 4);
        }
        __syncthreads();
        for (int j = 0; j < cnt; j++) {
            float w = ((const float*)&w_s[j])[h];
            acc += w * g_feats[dst_s[j] * CO + t];
            wsum += w;
        }
        __syncthreads();
    }
    out[n * CO + t] = acc / wsum;   // 0/0 -> NaN, matching reference
}

extern "C" void kernel_launch(void* const* d_in, const int* in_sizes, int n_in,
                              void* d_out, int out_size) {
    const float* x    = (const float*)d_in[0];
    const int*   idx  = (const int*)d_in[1];
    const float* elem = (const float*)d_in[2];
    const float* Ws   = (const float*)d_in[3];
    const float* bs   = (const float*)d_in[4];
    const float* aw   = (const float*)d_in[5];
    const float* ab   = (const float*)d_in[6];
    float* out = (float*)d_out;

    prep_kernel<<<(DI * CO + 255) / 256, 256>>>(Ws, bs);
    zero_deg_kernel<<<(NN + 255) / 256, 256>>>();
    count_kernel<<<(NE + 255) / 256, 256>>>(idx);
    gemm_kernel<<<dim3(CO / 64, (NN + 63) / 64), 256>>>(x);
    attn_kernel<<<(NN * 32 + 255) / 256, 256>>>(aw);
    scan_kernel<<<1, 1024>>>();
    edge_kernel<<<(NE + 255) / 256, 256>>>(idx, elem, aw, ab);
    gather_kernel<<<NN, 256>>>(idx, out);
}

// round 2
// speedup vs baseline: 1.1794x; 1.1794x over previous
#include <cuda_runtime.h>

#define NN 50000
#define NE 800000
#define NH 4
#define DI 256
#define DO 64
#define CO 256   // NH * DO

#define BM 128
#define BN 128
#define BK 8
#define NB_SCAN 196  // ceil(NN/256)

// ---- scratch (device globals; no runtime allocation) ----
__device__ float g_feats[NN * CO];       // [n][h*64+o]
__device__ float g_as[NN * NH];
__device__ float g_ad[NN * NH];
__device__ float g_w[NE * NH];           // [e][h], float4-aligned per edge
__device__ int   g_deg[NN];
__device__ int   g_rowstart[NN + 1];
__device__ int   g_cursor[NN];
__device__ int   g_eidx[NE];
__device__ float g_Wcat[DI * CO];        // [d][h*64+o]
__device__ float g_bcat[CO];
__device__ int   g_part[NB_SCAN];

// ---------------- weight repack ----------------
__global__ void prep_kernel(const float* __restrict__ Ws, const float* __restrict__ bs) {
    int i = blockIdx.x * blockDim.x + threadIdx.x;
    if (i < DI * CO) {
        int d = i >> 8, c = i & 255;
        int h = c >> 6, o = c & 63;
        g_Wcat[i] = Ws[(h * DI + d) * DO + o];
    }
    if (i < CO) {
        int h = i >> 6, o = i & 63;
        g_bcat[i] = bs[h * DO + o];
    }
}

__global__ void zero_deg_kernel() {
    int i = blockIdx.x * blockDim.x + threadIdx.x;
    if (i < NN) g_deg[i] = 0;
}

__global__ void count_kernel(const int* __restrict__ idx) {
    int e = blockIdx.x * blockDim.x + threadIdx.x;
    if (e < NE) atomicAdd(&g_deg[idx[e]], 1);
}

// ---------------- 3-phase decoupled scan ----------------
__global__ void scan1_kernel() {           // per-block reduce
    __shared__ int sd[256];
    int tid = threadIdx.x;
    int i = blockIdx.x * 256 + tid;
    sd[tid] = (i < NN) ? g_deg[i] : 0;
    __syncthreads();
    for (int off = 128; off; off >>= 1) {
        if (tid < off) sd[tid] += sd[tid + off];
        __syncthreads();
    }
    if (tid == 0) g_part[blockIdx.x] = sd[0];
}

__global__ void scan2_kernel() {           // scan partials (1 block, 256 thr)
    __shared__ int sd[256];
    int tid = threadIdx.x;
    int v = (tid < NB_SCAN) ? g_part[tid] : 0;
    sd[tid] = v;
    __syncthreads();
    for (int off = 1; off < 256; off <<= 1) {
        int t = (tid >= off) ? sd[tid - off] : 0;
        __syncthreads();
        sd[tid] += t;
        __syncthreads();
    }
    if (tid < NB_SCAN) g_part[tid] = sd[tid] - v;  // exclusive
    if (tid == 255) g_rowstart[NN] = sd[255];
}

__global__ void scan3_kernel() {           // per-block exclusive scan + offset
    __shared__ int sd[256];
    int tid = threadIdx.x;
    int i = blockIdx.x * 256 + tid;
    int v = (i < NN) ? g_deg[i] : 0;
    sd[tid] = v;
    __syncthreads();
    for (int off = 1; off < 256; off <<= 1) {
        int t = (tid >= off) ? sd[tid - off] : 0;
        __syncthreads();
        sd[tid] += t;
        __syncthreads();
    }
    if (i < NN) {
        int ex = g_part[blockIdx.x] + sd[tid] - v;
        g_rowstart[i] = ex;
        g_cursor[i] = ex;
    }
}

// ---------------- projection GEMM: feats = x @ Wcat + bcat ----------------
// 128x128 tile, 256 threads, 8x8 register blocking, BK=8
__global__ void __launch_bounds__(256) gemm_kernel(const float* __restrict__ x) {
    __shared__ float As[BK][BM + 4];   // [k][m]
    __shared__ float Bs[BK][BN + 4];   // [k][n]
    int tid = threadIdx.x;
    int tx = tid & 15;        // 0..15
    int ty = tid >> 4;        // 0..15
    int bm = blockIdx.y * BM;
    int bn = blockIdx.x * BN;

    int arow = tid >> 1;          // 0..127
    int acol = (tid & 1) * 4;     // 0 or 4
    int bkr  = tid >> 5;          // 0..7
    int bnc  = (tid & 31) * 4;    // 0..124

    int grow = bm + arow;
    bool arow_ok = grow < NN;
    const float* xp = x + (size_t)grow * DI + acol;
    const float* bp = g_Wcat + bkr * CO + bn + bnc;

    float acc[8][8] = {};

    for (int k0 = 0; k0 < DI; k0 += BK) {
        float4 av = arow_ok ? *(const float4*)(xp + k0)
                            : make_float4(0.f, 0.f, 0.f, 0.f);
        As[acol + 0][arow] = av.x;
        As[acol + 1][arow] = av.y;
        As[acol + 2][arow] = av.z;
        As[acol + 3][arow] = av.w;
        *(float4*)&Bs[bkr][bnc] = *(const float4*)(bp + k0 * CO);
        __syncthreads();

#pragma unroll
        for (int k = 0; k < BK; k++) {
            float a[8], b[8];
            *(float4*)(a)     = *(const float4*)&As[k][ty * 8];
            *(float4*)(a + 4) = *(const float4*)&As[k][ty * 8 + 4];
            *(float4*)(b)     = *(const float4*)&Bs[k][tx * 8];
            *(float4*)(b + 4) = *(const float4*)&Bs[k][tx * 8 + 4];
#pragma unroll
            for (int i = 0; i < 8; i++)
#pragma unroll
                for (int j = 0; j < 8; j++)
                    acc[i][j] += a[i] * b[j];
        }
        __syncthreads();
    }

#pragma unroll
    for (int i = 0; i < 8; i++) {
        int row = bm + ty * 8 + i;
        if (row < NN) {
            float* op = g_feats + (size_t)row * CO + bn + tx * 8;
            const float* bb = g_bcat + bn + tx * 8;
            float4 o0 = make_float4(acc[i][0] + bb[0], acc[i][1] + bb[1],
                                    acc[i][2] + bb[2], acc[i][3] + bb[3]);
            float4 o1 = make_float4(acc[i][4] + bb[4], acc[i][5] + bb[5],
                                    acc[i][6] + bb[6], acc[i][7] + bb[7]);
            *(float4*)(op)     = o0;
            *(float4*)(op + 4) = o1;
        }
    }
}

// ---------------- per-node attention dots: a_s, a_d ----------------
__global__ void attn_kernel(const float* __restrict__ aw) {
    int gw = (blockIdx.x * blockDim.x + threadIdx.x) >> 5;
    int lane = threadIdx.x & 31;
    if (gw >= NN) return;
    const float* f = g_feats + (size_t)gw * CO;
#pragma unroll
    for (int h = 0; h < NH; h++) {
        float f0 = f[h * 64 + lane];
        float f1 = f[h * 64 + 32 + lane];
        const float* a = aw + h * (2 * DO + 1);
        float vs = f0 * a[lane] + f1 * a[32 + lane];
        float vd = f0 * a[64 + lane] + f1 * a[96 + lane];
#pragma unroll
        for (int off = 16; off; off >>= 1) {
            vs += __shfl_down_sync(0xffffffffu, vs, off);
            vd += __shfl_down_sync(0xffffffffu, vd, off);
        }
        if (lane == 0) {
            g_as[gw * NH + h] = vs;
            g_ad[gw * NH + h] = vd;
        }
    }
}

// ---------------- edge weights + CSR fill ----------------
__global__ void edge_kernel(const int* __restrict__ idx, const float* __restrict__ elem,
                            const float* __restrict__ aw, const float* __restrict__ ab) {
    int e = blockIdx.x * blockDim.x + threadIdx.x;
    if (e >= NE) return;
    int s = idx[e];
    int d = idx[NE + e];
    float el = elem[e];
    float w[NH];
#pragma unroll
    for (int h = 0; h < NH; h++) {
        float sc = g_as[s * NH + h] + g_ad[d * NH + h]
                 + aw[h * (2 * DO + 1) + 2 * DO] * el + ab[h];
        sc = sc * (1.0f / 20.0f);
        w[h] = __expf(-fmaxf(sc, 0.0f));
    }
    *(float4*)(g_w + e * 4) = make_float4(w[0], w[1], w[2], w[3]);
    int pos = atomicAdd(&g_cursor[s], 1);
    g_eidx[pos] = e;
}

// ---------------- per-node gather + normalize ----------------
__global__ void __launch_bounds__(256) gather_kernel(const int* __restrict__ idx,
                                                     float* __restrict__ out) {
    int n = blockIdx.x;
    int t = threadIdx.x;          // 0..255 = h*64+o
    int h = t >> 6;
    int start = g_rowstart[n];
    int end = g_rowstart[n + 1];

    __shared__ int    dst_s[64];
    __shared__ float4 w_s[64];

    float acc = 0.f, wsum = 0.f;
    for (int base = start; base < end; base += 64) {
        int cnt = min(64, end - base);
        if (t < cnt) {
            int e = g_eidx[base + t];
            dst_s[t] = idx[NE + e];
            w_s[t] = *(const float4*)(g_w + e * 4);
        }
        __syncthreads();
#pragma unroll 4
        for (int j = 0; j < cnt; j++) {
            float w = ((const float*)&w_s[j])[h];
            acc += w * g_feats[(size_t)dst_s[j] * CO + t];
            wsum += w;
        }
        __syncthreads();
    }
    out[(size_t)n * CO + t] = acc / wsum;   // 0/0 -> NaN, matching reference
}

extern "C" void kernel_launch(void* const* d_in, const int* in_sizes, int n_in,
                              void* d_out, int out_size) {
    const float* x    = (const float*)d_in[0];
    const int*   idx  = (const int*)d_in[1];
    const float* elem = (const float*)d_in[2];
    const float* Ws   = (const float*)d_in[3];
    const float* bs   = (const float*)d_in[4];
    const float* aw   = (const float*)d_in[5];
    const float* ab   = (const float*)d_in[6];
    float* out = (float*)d_out;

    prep_kernel<<<(DI * CO + 255) / 256, 256>>>(Ws, bs);
    zero_deg_kernel<<<(NN + 255) / 256, 256>>>();
    count_kernel<<<(NE + 255) / 256, 256>>>(idx);
    scan1_kernel<<<NB_SCAN, 256>>>();
    scan2_kernel<<<1, 256>>>();
    scan3_kernel<<<NB_SCAN, 256>>>();
    gemm_kernel<<<dim3(CO / BN, (NN + BM - 1) / BM), 256>>>(x);
    attn_kernel<<<(NN * 32 + 255) / 256, 256>>>(aw);
    edge_kernel<<<(NE + 255) / 256, 256>>>(idx, elem, aw, ab);
    gather_kernel<<<NN, 256>>>(idx, out);
}

// round 3
// speedup vs baseline: 1.4759x; 1.2515x over previous
#include <cuda_runtime.h>

#define NN 50000
#define NE 800000
#define NH 4
#define DI 256
#define DO 64
#define CO 256   // NH * DO

#define BM 128
#define BN 128
#define BK 8
#define NB_SCAN 196  // ceil(NN/256)

// ---- scratch (device globals; no runtime allocation) ----
__device__ float g_feats[NN * CO];       // [n][h*64+o]
__device__ float4 g_as4[NN];             // per-node src dots (4 heads)
__device__ float4 g_ad4[NN];             // per-node dst dots
__device__ float g_w[NE * NH];           // CSR-ordered weights [pos][h]
__device__ int   g_cdst[NE];             // CSR-ordered dst
__device__ int   g_deg[NN];
__device__ int   g_rowstart[NN + 1];
__device__ int   g_cursor[NN];
__device__ float g_Wcat[DI * CO];        // [d][h*64+o]
__device__ float g_bcat[CO];
__device__ int   g_part[NB_SCAN];
__device__ float g_v[8 * DI];            // j = h*2+sd : W[h]@aw_{src/dst}[h]
__device__ float g_c[8];                 // bs[h]·aw_{src/dst}[h]

// ---------------- weight repack ----------------
__global__ void prep_kernel(const float* __restrict__ Ws, const float* __restrict__ bs) {
    int i = blockIdx.x * blockDim.x + threadIdx.x;
    if (i < DI * CO) {
        int d = i >> 8, c = i & 255;
        int h = c >> 6, o = c & 63;
        g_Wcat[i] = Ws[(h * DI + d) * DO + o];
    }
    if (i < CO) {
        int h = i >> 6, o = i & 63;
        g_bcat[i] = bs[h * DO + o];
    }
}

// v[j][d] = sum_o Ws[h][d][o] * aw[h][sd*64+o],  c[j] = sum_o bs[h][o]*aw[h][sd*64+o]
__global__ void prepv_kernel(const float* __restrict__ Ws, const float* __restrict__ bs,
                             const float* __restrict__ aw) {
    int id = blockIdx.x * blockDim.x + threadIdx.x;
    if (id < 8 * DI) {
        int j = id >> 8, d = id & 255;
        int h = j >> 1, sd = j & 1;
        const float* wrow = Ws + (h * DI + d) * DO;
        const float* arow = aw + h * (2 * DO + 1) + sd * DO;
        float s = 0.f;
#pragma unroll
        for (int o = 0; o < DO; o++) s += wrow[o] * arow[o];
        g_v[id] = s;
    } else if (id < 8 * DI + 8) {
        int j = id - 8 * DI;
        int h = j >> 1, sd = j & 1;
        const float* arow = aw + h * (2 * DO + 1) + sd * DO;
        float s = 0.f;
#pragma unroll
        for (int o = 0; o < DO; o++) s += bs[h * DO + o] * arow[o];
        g_c[j] = s;
    }
}

__global__ void zero_deg_kernel() {
    int i = blockIdx.x * blockDim.x + threadIdx.x;
    if (i < NN) g_deg[i] = 0;
}

__global__ void count_kernel(const int* __restrict__ idx) {
    int e = blockIdx.x * blockDim.x + threadIdx.x;
    if (e < NE) atomicAdd(&g_deg[idx[e]], 1);
}

// ---------------- 3-phase decoupled scan ----------------
__global__ void scan1_kernel() {
    __shared__ int sd[256];
    int tid = threadIdx.x;
    int i = blockIdx.x * 256 + tid;
    sd[tid] = (i < NN) ? g_deg[i] : 0;
    __syncthreads();
    for (int off = 128; off; off >>= 1) {
        if (tid < off) sd[tid] += sd[tid + off];
        __syncthreads();
    }
    if (tid == 0) g_part[blockIdx.x] = sd[0];
}

__global__ void scan2_kernel() {
    __shared__ int sd[256];
    int tid = threadIdx.x;
    int v = (tid < NB_SCAN) ? g_part[tid] : 0;
    sd[tid] = v;
    __syncthreads();
    for (int off = 1; off < 256; off <<= 1) {
        int t = (tid >= off) ? sd[tid - off] : 0;
        __syncthreads();
        sd[tid] += t;
        __syncthreads();
    }
    if (tid < NB_SCAN) g_part[tid] = sd[tid] - v;
    if (tid == 255) g_rowstart[NN] = sd[255];
}

__global__ void scan3_kernel() {
    __shared__ int sd[256];
    int tid = threadIdx.x;
    int i = blockIdx.x * 256 + tid;
    int v = (i < NN) ? g_deg[i] : 0;
    sd[tid] = v;
    __syncthreads();
    for (int off = 1; off < 256; off <<= 1) {
        int t = (tid >= off) ? sd[tid - off] : 0;
        __syncthreads();
        sd[tid] += t;
        __syncthreads();
    }
    if (i < NN) {
        int ex = g_part[blockIdx.x] + sd[tid] - v;
        g_rowstart[i] = ex;
        g_cursor[i] = ex;
    }
}

// ---------------- a_s/a_d directly from x: warp per node ----------------
__global__ void __launch_bounds__(256) as_kernel(const float* __restrict__ x) {
    int gw = (blockIdx.x * blockDim.x + threadIdx.x) >> 5;
    int lane = threadIdx.x & 31;
    if (gw >= NN) return;
    const float* xr = x + (size_t)gw * DI;
    float a[8] = {};
#pragma unroll
    for (int c8 = 0; c8 < 8; c8++) {
        float xv = xr[c8 * 32 + lane];
#pragma unroll
        for (int j = 0; j < 8; j++)
            a[j] += xv * __ldg(&g_v[j * DI + c8 * 32 + lane]);
    }
#pragma unroll
    for (int j = 0; j < 8; j++) {
#pragma unroll
        for (int off = 16; off; off >>= 1)
            a[j] += __shfl_xor_sync(0xffffffffu, a[j], off);
    }
    if (lane == 0) {
        g_as4[gw] = make_float4(a[0] + g_c[0], a[2] + g_c[2],
                                a[4] + g_c[4], a[6] + g_c[6]);
        g_ad4[gw] = make_float4(a[1] + g_c[1], a[3] + g_c[3],
                                a[5] + g_c[5], a[7] + g_c[7]);
    }
}

// ---------------- projection GEMM: feats = x @ Wcat + bcat ----------------
// 128x128 tile, 256 threads, 8x8 register blocking, BK=8, double-buffered smem
__global__ void __launch_bounds__(256, 2) gemm_kernel(const float* __restrict__ x) {
    __shared__ float As[2][BK][BM + 4];
    __shared__ float Bs[2][BK][BN + 4];
    int tid = threadIdx.x;
    int tx = tid & 15;
    int ty = tid >> 4;
    int bm = blockIdx.y * BM;
    int bn = blockIdx.x * BN;

    int am = tid >> 1;            // 0..127
    int akc = (tid & 1) * 4;      // 0 or 4
    int bkr = tid >> 5;           // 0..7
    int bnc = (tid & 31) * 4;     // 0..124

    int grow = bm + am;
    bool aok = grow < NN;
    const float* xp = x + (size_t)grow * DI + akc;
    const float* bp = g_Wcat + bkr * CO + bn + bnc;

    float4 ar = aok ? *(const float4*)(xp) : make_float4(0.f, 0.f, 0.f, 0.f);
    float4 br = *(const float4*)(bp);
    As[0][akc + 0][am] = ar.x;
    As[0][akc + 1][am] = ar.y;
    As[0][akc + 2][am] = ar.z;
    As[0][akc + 3][am] = ar.w;
    *(float4*)&Bs[0][bkr][bnc] = br;
    __syncthreads();

    float acc[8][8] = {};
    int buf = 0;

    for (int k0 = BK; k0 < DI; k0 += BK) {
        ar = aok ? *(const float4*)(xp + k0) : make_float4(0.f, 0.f, 0.f, 0.f);
        br = *(const float4*)(bp + k0 * CO);
#pragma unroll
        for (int k = 0; k < BK; k++) {
            float a[8], b[8];
            *(float4*)(a)     = *(const float4*)&As[buf][k][ty * 8];
            *(float4*)(a + 4) = *(const float4*)&As[buf][k][ty * 8 + 4];
            *(float4*)(b)     = *(const float4*)&Bs[buf][k][tx * 8];
            *(float4*)(b + 4) = *(const float4*)&Bs[buf][k][tx * 8 + 4];
#pragma unroll
            for (int i = 0; i < 8; i++)
#pragma unroll
                for (int j = 0; j < 8; j++)
                    acc[i][j] += a[i] * b[j];
        }
        As[buf ^ 1][akc + 0][am] = ar.x;
        As[buf ^ 1][akc + 1][am] = ar.y;
        As[buf ^ 1][akc + 2][am] = ar.z;
        As[buf ^ 1][akc + 3][am] = ar.w;
        *(float4*)&Bs[buf ^ 1][bkr][bnc] = br;
        __syncthreads();
        buf ^= 1;
    }
#pragma unroll
    for (int k = 0; k < BK; k++) {
        float a[8], b[8];
        *(float4*)(a)     = *(const float4*)&As[buf][k][ty * 8];
        *(float4*)(a + 4) = *(const float4*)&As[buf][k][ty * 8 + 4];
        *(float4*)(b)     = *(const float4*)&Bs[buf][k][tx * 8];
        *(float4*)(b + 4) = *(const float4*)&Bs[buf][k][tx * 8 + 4];
#pragma unroll
        for (int i = 0; i < 8; i++)
#pragma unroll
            for (int j = 0; j < 8; j++)
                acc[i][j] += a[i] * b[j];
    }

#pragma unroll
    for (int i = 0; i < 8; i++) {
        int row = bm + ty * 8 + i;
        if (row < NN) {
            float* op = g_feats + (size_t)row * CO + bn + tx * 8;
            const float* bb = g_bcat + bn + tx * 8;
            float4 o0 = make_float4(acc[i][0] + bb[0], acc[i][1] + bb[1],
                                    acc[i][2] + bb[2], acc[i][3] + bb[3]);
            float4 o1 = make_float4(acc[i][4] + bb[4], acc[i][5] + bb[5],
                                    acc[i][6] + bb[6], acc[i][7] + bb[7]);
            *(float4*)(op)     = o0;
            *(float4*)(op + 4) = o1;
        }
    }
}

// ---------------- edge weights + flat CSR fill ----------------
__global__ void edge_kernel(const int* __restrict__ idx, const float* __restrict__ elem,
                            const float* __restrict__ aw, const float* __restrict__ ab) {
    int e = blockIdx.x * blockDim.x + threadIdx.x;
    if (e >= NE) return;
    int s = idx[e];
    int d = idx[NE + e];
    float el = elem[e];
    float4 as = __ldg(&g_as4[s]);
    float4 ad = __ldg(&g_ad4[d]);
    const float* asv = (const float*)&as;
    const float* adv = (const float*)&ad;
    float w[NH];
#pragma unroll
    for (int h = 0; h < NH; h++) {
        float sc = asv[h] + adv[h]
                 + __ldg(&aw[h * (2 * DO + 1) + 2 * DO]) * el + __ldg(&ab[h]);
        sc = sc * (1.0f / 20.0f);
        w[h] = __expf(-fmaxf(sc, 0.0f));
    }
    int pos = atomicAdd(&g_cursor[s], 1);
    g_cdst[pos] = d;
    *(float4*)(g_w + (size_t)pos * 4) = make_float4(w[0], w[1], w[2], w[3]);
}

// ---------------- per-node gather + normalize (64 thr/node, 4 nodes/block) ----------------
__global__ void __launch_bounds__(256) gather_kernel(float* __restrict__ out) {
    int t = threadIdx.x;
    int n = blockIdx.x * 4 + (t >> 6);
    int l = t & 63;
    int h = l >> 4;
    int start = g_rowstart[n];
    int end = g_rowstart[n + 1];

    const float4* fp = (const float4*)g_feats;
    float4 acc = make_float4(0.f, 0.f, 0.f, 0.f);
    float wsum = 0.f;

#pragma unroll 4
    for (int j = start; j < end; j++) {
        int dst = __ldg(&g_cdst[j]);
        float w = __ldg(&g_w[(size_t)j * 4 + h]);
        float4 f = __ldg(fp + (size_t)dst * 64 + l);
        acc.x += w * f.x;
        acc.y += w * f.y;
        acc.z += w * f.z;
        acc.w += w * f.w;
        wsum += w;
    }
    float4 o = make_float4(acc.x / wsum, acc.y / wsum, acc.z / wsum, acc.w / wsum);
    *(float4*)(out + (size_t)n * CO + l * 4) = o;   // 0/0 -> NaN, matching reference
}

extern "C" void kernel_launch(void* const* d_in, const int* in_sizes, int n_in,
                              void* d_out, int out_size) {
    const float* x    = (const float*)d_in[0];
    const int*   idx  = (const int*)d_in[1];
    const float* elem = (const float*)d_in[2];
    const float* Ws   = (const float*)d_in[3];
    const float* bs   = (const float*)d_in[4];
    const float* aw   = (const float*)d_in[5];
    const float* ab   = (const float*)d_in[6];
    float* out = (float*)d_out;

    prep_kernel<<<(DI * CO + 255) / 256, 256>>>(Ws, bs);
    prepv_kernel<<<(8 * DI + 8 + 255) / 256, 256>>>(Ws, bs, aw);
    zero_deg_kernel<<<(NN + 255) / 256, 256>>>();
    count_kernel<<<(NE + 255) / 256, 256>>>(idx);
    scan1_kernel<<<NB_SCAN, 256>>>();
    scan2_kernel<<<1, 256>>>();
    scan3_kernel<<<NB_SCAN, 256>>>();
    as_kernel<<<(NN * 32 + 255) / 256, 256>>>(x);
    edge_kernel<<<(NE + 255) / 256, 256>>>(idx, elem, aw, ab);
    gemm_kernel<<<dim3(CO / BN, (NN + BM - 1) / BM), 256>>>(x);
    gather_kernel<<<NN / 4, 256>>>(out);
}

// round 5
// speedup vs baseline: 2.3093x; 1.5647x over previous
#include <cuda_runtime.h>
#include <cuda_bf16.h>
#include <cstdint>

#define NN 50000
#define NE 800000
#define NH 4
#define DI 256
#define DO 64
#define CO 256   // NH * DO

#define NB_SCAN 196  // ceil(NN/256)

// ---- scratch (device globals; no runtime allocation) ----
__device__ float g_feats[NN * CO];       // [n][h*64+o]
__device__ float4 g_as4[NN];
__device__ float4 g_ad4[NN];
__device__ float g_w[NE * NH];           // CSR-ordered weights [pos][h]
__device__ int   g_cdst[NE];
__device__ int   g_deg[NN];
__device__ int   g_rowstart[NN + 1];
__device__ int   g_cursor[NN];
__device__ float g_bcat[CO];
__device__ int   g_part[NB_SCAN];
__device__ float g_v[8 * DI];
__device__ float g_c[8];
__device__ __nv_bfloat16 g_Bhi[CO * DI]; // Bt[n][k] hi  (n = h*64+o, k = d)
__device__ __nv_bfloat16 g_Blo[CO * DI]; // Bt[n][k] lo

// ==================== small prep kernels ====================
__global__ void prep_kernel(const float* __restrict__ bs) {
    int i = blockIdx.x * blockDim.x + threadIdx.x;
    if (i < CO) {
        int h = i >> 6, o = i & 63;
        g_bcat[i] = bs[h * DO + o];
    }
}

// B transposed + bf16 split: Bt[n][k] = Ws[h][k][o], n = h*64+o
__global__ void prepB_kernel(const float* __restrict__ Ws) {
    int i = blockIdx.x * blockDim.x + threadIdx.x;
    if (i >= CO * DI) return;
    int n = i >> 8, k = i & 255;
    int h = n >> 6, o = n & 63;
    float v = Ws[(h * DI + k) * DO + o];
    __nv_bfloat16 hi = __float2bfloat16(v);
    __nv_bfloat16 lo = __float2bfloat16(v - __bfloat162float(hi));
    g_Bhi[i] = hi;
    g_Blo[i] = lo;
}

__global__ void prepv_kernel(const float* __restrict__ Ws, const float* __restrict__ bs,
                             const float* __restrict__ aw) {
    int id = blockIdx.x * blockDim.x + threadIdx.x;
    if (id < 8 * DI) {
        int j = id >> 8, d = id & 255;
        int h = j >> 1, sd = j & 1;
        const float* wrow = Ws + (h * DI + d) * DO;
        const float* arow = aw + h * (2 * DO + 1) + sd * DO;
        float s = 0.f;
#pragma unroll
        for (int o = 0; o < DO; o++) s += wrow[o] * arow[o];
        g_v[id] = s;
    } else if (id < 8 * DI + 8) {
        int j = id - 8 * DI;
        int h = j >> 1, sd = j & 1;
        const float* arow = aw + h * (2 * DO + 1) + sd * DO;
        float s = 0.f;
#pragma unroll
        for (int o = 0; o < DO; o++) s += bs[h * DO + o] * arow[o];
        g_c[j] = s;
    }
}

__global__ void zero_deg_kernel() {
    int i = blockIdx.x * blockDim.x + threadIdx.x;
    if (i < NN) g_deg[i] = 0;
}

__global__ void count_kernel(const int* __restrict__ idx) {
    int e = blockIdx.x * blockDim.x + threadIdx.x;
    if (e < NE) atomicAdd(&g_deg[idx[e]], 1);
}

// ---------------- 3-phase decoupled scan ----------------
__global__ void scan1_kernel() {
    __shared__ int sd[256];
    int tid = threadIdx.x;
    int i = blockIdx.x * 256 + tid;
    sd[tid] = (i < NN) ? g_deg[i] : 0;
    __syncthreads();
    for (int off = 128; off; off >>= 1) {
        if (tid < off) sd[tid] += sd[tid + off];
        __syncthreads();
    }
    if (tid == 0) g_part[blockIdx.x] = sd[0];
}

__global__ void scan2_kernel() {
    __shared__ int sd[256];
    int tid = threadIdx.x;
    int v = (tid < NB_SCAN) ? g_part[tid] : 0;
    sd[tid] = v;
    __syncthreads();
    for (int off = 1; off < 256; off <<= 1) {
        int t = (tid >= off) ? sd[tid - off] : 0;
        __syncthreads();
        sd[tid] += t;
        __syncthreads();
    }
    if (tid < NB_SCAN) g_part[tid] = sd[tid] - v;
    if (tid == 255) g_rowstart[NN] = sd[255];
}

__global__ void scan3_kernel() {
    __shared__ int sd[256];
    int tid = threadIdx.x;
    int i = blockIdx.x * 256 + tid;
    int v = (i < NN) ? g_deg[i] : 0;
    sd[tid] = v;
    __syncthreads();
    for (int off = 1; off < 256; off <<= 1) {
        int t = (tid >= off) ? sd[tid - off] : 0;
        __syncthreads();
        sd[tid] += t;
        __syncthreads();
    }
    if (i < NN) {
        int ex = g_part[blockIdx.x] + sd[tid] - v;
        g_rowstart[i] = ex;
        g_cursor[i] = ex;
    }
}

// ---------------- a_s/a_d directly from x: warp per node ----------------
__global__ void __launch_bounds__(256) as_kernel(const float* __restrict__ x) {
    int gw = (blockIdx.x * blockDim.x + threadIdx.x) >> 5;
    int lane = threadIdx.x & 31;
    if (gw >= NN) return;
    const float* xr = x + (size_t)gw * DI;
    float a[8] = {};
#pragma unroll
    for (int c8 = 0; c8 < 8; c8++) {
        float xv = xr[c8 * 32 + lane];
#pragma unroll
        for (int j = 0; j < 8; j++)
            a[j] += xv * __ldg(&g_v[j * DI + c8 * 32 + lane]);
    }
#pragma unroll
    for (int j = 0; j < 8; j++) {
#pragma unroll
        for (int off = 16; off; off >>= 1)
            a[j] += __shfl_xor_sync(0xffffffffu, a[j], off);
    }
    if (lane == 0) {
        g_as4[gw] = make_float4(a[0] + g_c[0], a[2] + g_c[2],
                                a[4] + g_c[4], a[6] + g_c[6]);
        g_ad4[gw] = make_float4(a[1] + g_c[1], a[3] + g_c[3],
                                a[5] + g_c[5], a[7] + g_c[7]);
    }
}

// ==================== warp-level bf16 split MMA GEMM ====================
// feats[128 rows][128 cols per CTA] ; grid = (2, ceil(NN/128))
// 8 warps, warp tile 32(M) x 64(N), K chunks of 32, smem row stride 40 bf16 (80B)
#define KS 32          // k-chunk
#define LDA 40         // smem row stride in bf16 elements

__device__ __forceinline__ void mma_bf16(float* c, const uint32_t* a, const uint32_t* b) {
    asm volatile(
        "mma.sync.aligned.m16n8k16.row.col.f32.bf16.bf16.f32 "
        "{%0,%1,%2,%3}, {%4,%5,%6,%7}, {%8,%9}, {%0,%1,%2,%3};"
        : "+f"(c[0]), "+f"(c[1]), "+f"(c[2]), "+f"(c[3])
        : "r"(a[0]), "r"(a[1]), "r"(a[2]), "r"(a[3]), "r"(b[0]), "r"(b[1]));
}

__global__ void __launch_bounds__(256, 2) gemm_mma_kernel(const float* __restrict__ x) {
    __shared__ __align__(16) __nv_bfloat16 sAhi[128 * LDA];
    __shared__ __align__(16) __nv_bfloat16 sAlo[128 * LDA];
    __shared__ __align__(16) __nv_bfloat16 sBhi[128 * LDA];
    __shared__ __align__(16) __nv_bfloat16 sBlo[128 * LDA];

    int tid = threadIdx.x;
    int wid = tid >> 5;
    int lane = tid & 31;
    int group = lane >> 2;       // 0..7
    int tid4 = lane & 3;         // 0..3
    int bm = blockIdx.y * 128;
    int bn = blockIdx.x * 128;
    int wm = (wid & 3) * 32;     // warp M offset
    int wn = (wid >> 2) * 64;    // warp N offset

    // global load mapping: row = tid>>1 (0..127), k0 = (tid&1)*16
    int lrow = tid >> 1;
    int lk0 = (tid & 1) * 16;
    int grow = bm + lrow;
    bool aok = grow < NN;
    const float4* xp = (const float4*)(x + (size_t)grow * DI);
    const uint4* bhp = (const uint4*)(g_Bhi + (size_t)(bn + lrow) * DI);
    const uint4* blp = (const uint4*)(g_Blo + (size_t)(bn + lrow) * DI);

    float acc[2][8][4] = {};

    for (int c = 0; c < DI / KS; c++) {
        if (c) __syncthreads();
        int ck = c * KS;
        // ---- A: fp32 -> bf16 hi/lo into smem ----
#pragma unroll
        for (int q = 0; q < 4; q++) {
            float4 v = aok ? __ldg(xp + ((ck + lk0) >> 2) + q)
                           : make_float4(0.f, 0.f, 0.f, 0.f);
            __nv_bfloat16 h0 = __float2bfloat16(v.x);
            __nv_bfloat16 h1 = __float2bfloat16(v.y);
            __nv_bfloat16 h2 = __float2bfloat16(v.z);
            __nv_bfloat16 h3 = __float2bfloat16(v.w);
            __nv_bfloat162 hiA; hiA.x = h0; hiA.y = h1;
            __nv_bfloat162 hiB; hiB.x = h2; hiB.y = h3;
            __nv_bfloat162 loA, loB;
            loA.x = __float2bfloat16(v.x - __bfloat162float(h0));
            loA.y = __float2bfloat16(v.y - __bfloat162float(h1));
            loB.x = __float2bfloat16(v.z - __bfloat162float(h2));
            loB.y = __float2bfloat16(v.w - __bfloat162float(h3));
            int e = lrow * LDA + lk0 + q * 4;
            *(__nv_bfloat162*)&sAhi[e]     = hiA;
            *(__nv_bfloat162*)&sAhi[e + 2] = hiB;
            *(__nv_bfloat162*)&sAlo[e]     = loA;
            *(__nv_bfloat162*)&sAlo[e + 2] = loB;
        }
        // ---- B: pre-split bf16 hi/lo into smem ----
        {
            uint4 vh0 = __ldg(bhp + ((ck + lk0) >> 3));
            uint4 vh1 = __ldg(bhp + ((ck + lk0) >> 3) + 1);
            uint4 vl0 = __ldg(blp + ((ck + lk0) >> 3));
            uint4 vl1 = __ldg(blp + ((ck + lk0) >> 3) + 1);
            int e = lrow * LDA + lk0;
            *(uint4*)&sBhi[e]     = vh0;
            *(uint4*)&sBhi[e + 8] = vh1;
            *(uint4*)&sBlo[e]     = vl0;
            *(uint4*)&sBlo[e + 8] = vl1;
        }
        __syncthreads();

        // ---- compute: 2 k16 steps ----
#pragma unroll
        for (int k16 = 0; k16 < KS; k16 += 16) {
            uint32_t ah[2][4], al[2][4];
#pragma unroll
            for (int mi = 0; mi < 2; mi++) {
                int r0 = (wm + mi * 16 + group) * LDA + k16 + tid4 * 2;
                ah[mi][0] = *(const uint32_t*)&sAhi[r0];
                ah[mi][1] = *(const uint32_t*)&sAhi[r0 + 8 * LDA];
                ah[mi][2] = *(const uint32_t*)&sAhi[r0 + 8];
                ah[mi][3] = *(const uint32_t*)&sAhi[r0 + 8 * LDA + 8];
                al[mi][0] = *(const uint32_t*)&sAlo[r0];
                al[mi][1] = *(const uint32_t*)&sAlo[r0 + 8 * LDA];
                al[mi][2] = *(const uint32_t*)&sAlo[r0 + 8];
                al[mi][3] = *(const uint32_t*)&sAlo[r0 + 8 * LDA + 8];
            }
#pragma unroll
            for (int ni = 0; ni < 8; ni++) {
                int rb = (wn + ni * 8 + group) * LDA + k16 + tid4 * 2;
                uint32_t bh[2], bl[2];
                bh[0] = *(const uint32_t*)&sBhi[rb];
                bh[1] = *(const uint32_t*)&sBhi[rb + 8];
                bl[0] = *(const uint32_t*)&sBlo[rb];
                bl[1] = *(const uint32_t*)&sBlo[rb + 8];
#pragma unroll
                for (int mi = 0; mi < 2; mi++) {
                    mma_bf16(acc[mi][ni], ah[mi], bh);
                    mma_bf16(acc[mi][ni], ah[mi], bl);
                    mma_bf16(acc[mi][ni], al[mi], bh);
                }
            }
        }
    }

    // ---- epilogue: add bias, store fp32 ----
#pragma unroll
    for (int mi = 0; mi < 2; mi++) {
        int row0 = bm + wm + mi * 16 + group;
        int row1 = row0 + 8;
#pragma unroll
        for (int ni = 0; ni < 8; ni++) {
            int col = bn + wn + ni * 8 + tid4 * 2;
            float2 bb = *(const float2*)(g_bcat + col);
            if (row0 < NN) {
                float2 o0 = make_float2(acc[mi][ni][0] + bb.x, acc[mi][ni][1] + bb.y);
                *(float2*)(g_feats + (size_t)row0 * CO + col) = o0;
            }
            if (row1 < NN) {
                float2 o1 = make_float2(acc[mi][ni][2] + bb.x, acc[mi][ni][3] + bb.y);
                *(float2*)(g_feats + (size_t)row1 * CO + col) = o1;
            }
        }
    }
}

// ---------------- edge weights + flat CSR fill ----------------
__global__ void edge_kernel(const int* __restrict__ idx, const float* __restrict__ elem,
                            const float* __restrict__ aw, const float* __restrict__ ab) {
    int e = blockIdx.x * blockDim.x + threadIdx.x;
    if (e >= NE) return;
    int s = idx[e];
    int d = idx[NE + e];
    float el = elem[e];
    float4 as = __ldg(&g_as4[s]);
    float4 ad = __ldg(&g_ad4[d]);
    const float* asv = (const float*)&as;
    const float* adv = (const float*)&ad;
    float w[NH];
#pragma unroll
    for (int h = 0; h < NH; h++) {
        float sc = asv[h] + adv[h]
                 + __ldg(&aw[h * (2 * DO + 1) + 2 * DO]) * el + __ldg(&ab[h]);
        sc = sc * (1.0f / 20.0f);
        w[h] = __expf(-fmaxf(sc, 0.0f));
    }
    int pos = atomicAdd(&g_cursor[s], 1);
    g_cdst[pos] = d;
    *(float4*)(g_w + (size_t)pos * 4) = make_float4(w[0], w[1], w[2], w[3]);
}

// ---------------- per-node gather + normalize ----------------
__global__ void __launch_bounds__(256) gather_kernel(float* __restrict__ out) {
    int t = threadIdx.x;
    int n = blockIdx.x * 4 + (t >> 6);
    int l = t & 63;
    int h = l >> 4;
    int start = g_rowstart[n];
    int end = g_rowstart[n + 1];

    const float4* fp = (const float4*)g_feats;
    float4 acc = make_float4(0.f, 0.f, 0.f, 0.f);
    float wsum = 0.f;

#pragma unroll 4
    for (int j = start; j < end; j++) {
        int dst = __ldg(&g_cdst[j]);
        float w = __ldg(&g_w[(size_t)j * 4 + h]);
        float4 f = __ldg(fp + (size_t)dst * 64 + l);
        acc.x += w * f.x;
        acc.y += w * f.y;
        acc.z += w * f.z;
        acc.w += w * f.w;
        wsum += w;
    }
    float4 o = make_float4(acc.x / wsum, acc.y / wsum, acc.z / wsum, acc.w / wsum);
    *(float4*)(out + (size_t)n * CO + l * 4) = o;
}

extern "C" void kernel_launch(void* const* d_in, const int* in_sizes, int n_in,
                              void* d_out, int out_size) {
    const float* x    = (const float*)d_in[0];
    const int*   idx  = (const int*)d_in[1];
    const float* elem = (const float*)d_in[2];
    const float* Ws   = (const float*)d_in[3];
    const float* bs   = (const float*)d_in[4];
    const float* aw   = (const float*)d_in[5];
    const float* ab   = (const float*)d_in[6];
    float* out = (float*)d_out;

    static cudaStream_t s1 = nullptr;
    static cudaEvent_t evF = nullptr, evJ = nullptr;
    if (!s1) {   // created on the (uncaptured) correctness call, reused thereafter
        cudaStreamCreateWithFlags(&s1, cudaStreamNonBlocking);
        cudaEventCreateWithFlags(&evF, cudaEventDisableTiming);
        cudaEventCreateWithFlags(&evJ, cudaEventDisableTiming);
    }

    // fork: s1 runs the CSR/attention chain, legacy stream runs the GEMM chain
    cudaEventRecord(evF, 0);
    cudaStreamWaitEvent(s1, evF, 0);

    prepv_kernel<<<(8 * DI + 8 + 255) / 256, 256, 0, s1>>>(Ws, bs, aw);
    zero_deg_kernel<<<(NN + 255) / 256, 256, 0, s1>>>();
    count_kernel<<<(NE + 255) / 256, 256, 0, s1>>>(idx);
    scan1_kernel<<<NB_SCAN, 256, 0, s1>>>();
    scan2_kernel<<<1, 256, 0, s1>>>();
    scan3_kernel<<<NB_SCAN, 256, 0, s1>>>();
    as_kernel<<<(NN * 32 + 255) / 256, 256, 0, s1>>>(x);
    edge_kernel<<<(NE + 255) / 256, 256, 0, s1>>>(idx, elem, aw, ab);
    cudaEventRecord(evJ, s1);

    prep_kernel<<<1, 256>>>(bs);
    prepB_kernel<<<(CO * DI + 255) / 256, 256>>>(Ws);
    gemm_mma_kernel<<<dim3(2, (NN + 127) / 128), 256>>>(x);

    // join, then gather (needs feats + CSR + weights)
    cudaStreamWaitEvent(0, evJ, 0);
    gather_kernel<<<NN / 4, 256>>>(out);
}